// round 3
// baseline (speedup 1.0000x reference)
#include <cuda_runtime.h>

// SSKernelDiag: K[h,l] = 2*Re( sum_n Ct[h,n] * dA[h,n]^l )
// Shapes fixed by the problem: CH=1, H=1024, N=64, L=2048.

#define HH  1024
#define NN  64
#define LL  2048
#define TPB 128
#define LPT (LL / TPB)   // 16 consecutive l's per thread
#define NPOW 7           // 2^7 = 128 = TPB; dA^(LPT*t) via bits of t

// Scratch (allocation-free rule: __device__ globals)
__device__ float g_Ctr[HH * NN];
__device__ float g_Cti[HH * NN];
__device__ float g_dAr[HH * NN];
__device__ float g_dAi[HH * NN];
__device__ float g_Pr[NPOW][HH * NN];   // P_k = dA^(LPT * 2^k)
__device__ float g_Pi[NPOW][HH * NN];

// ---------------------------------------------------------------------------
// Setup: bilinear discretization + power table. 65536 threads, trivial cost.
// ---------------------------------------------------------------------------
__global__ void ssd_setup_kernel(const float* __restrict__ C_ri,
                                 const float* __restrict__ log_dt,
                                 const float* __restrict__ B_ri,
                                 const float* __restrict__ invA,
                                 const float* __restrict__ Aim,
                                 int n_ssm) {
    int idx = blockIdx.x * blockDim.x + threadIdx.x;
    if (idx >= HH * NN) return;
    int h = idx / NN;
    int n = idx - h * NN;
    int t = h % n_ssm;                 // 't n -> (v t) n' tiling
    int tn = t * NN + n;

    float Ar = -__expf(invA[tn]);
    float Ai = Aim[tn];
    float dt = __expf(log_dt[h]);

    float xr = 0.5f * Ar * dt;         // dtA/2 (real)
    float xi = 0.5f * Ai * dt;         // dtA/2 (imag)
    float dr = 1.0f - xr, di = -xi;    // denom = 1 - dtA/2
    float nr = 1.0f + xr, ni = xi;     // numer = 1 + dtA/2
    float inv = 1.0f / (dr * dr + di * di);

    // dA = numer / denom
    float dAr = (nr * dr + ni * di) * inv;
    float dAi = (ni * dr - nr * di) * inv;

    // Ct = 2 * (B*C) * dt / denom   (factor 2 from 2*Re folded in)
    float Br = B_ri[2 * tn], Bi = B_ri[2 * tn + 1];
    float Cr = C_ri[2 * idx], Ci = C_ri[2 * idx + 1];
    float br = Br * Cr - Bi * Ci;
    float bi = Br * Ci + Bi * Cr;
    float s = 2.0f * dt * inv;
    g_Ctr[idx] = s * (br * dr + bi * di);
    g_Cti[idx] = s * (bi * dr - br * di);
    g_dAr[idx] = dAr;
    g_dAi[idx] = dAi;

    // P_0 = dA^LPT (LPT=16 -> 4 squarings), then P_k = P_{k-1}^2
    float pr = dAr, pi = dAi;
#pragma unroll
    for (int k = 0; k < 4; k++) {
        float r = pr * pr - pi * pi;
        float im = 2.0f * pr * pi;
        pr = r; pi = im;
    }
    g_Pr[0][idx] = pr; g_Pi[0][idx] = pi;
#pragma unroll
    for (int k = 1; k < NPOW; k++) {
        float r = pr * pr - pi * pi;
        float im = 2.0f * pr * pi;
        pr = r; pi = im;
        g_Pr[k][idx] = pr; g_Pi[k][idx] = pi;
    }
}

// ---------------------------------------------------------------------------
// Main: one block per h. Thread t owns l in [t*LPT, t*LPT+LPT).
// Loops n over smem (broadcast reads). Hot loop: 1 complex mul + 1 FADD per l.
// ---------------------------------------------------------------------------
__global__ void __launch_bounds__(TPB)
ssd_main_kernel(float* __restrict__ K) {
    const int h = blockIdx.x;
    const int t = threadIdx.x;
    const int base = h * NN;

    __shared__ float sCtr[NN], sCti[NN], sAr[NN], sAi[NN];
    __shared__ float sPr[NPOW][NN], sPi[NPOW][NN];

    for (int i = t; i < NN; i += TPB) {
        sCtr[i] = g_Ctr[base + i];
        sCti[i] = g_Cti[base + i];
        sAr[i]  = g_dAr[base + i];
        sAi[i]  = g_dAi[base + i];
#pragma unroll
        for (int k = 0; k < NPOW; k++) {
            sPr[k][i] = g_Pr[k][base + i];
            sPi[k][i] = g_Pi[k][base + i];
        }
    }
    __syncthreads();

    float acc[LPT];
#pragma unroll
    for (int j = 0; j < LPT; j++) acc[j] = 0.0f;

    for (int n = 0; n < NN; n++) {
        float wr = sCtr[n], wi = sCti[n];
        const float ar = sAr[n], ai = sAi[n];

        // w = Ct * dA^(LPT*t) via the squaring table (predicated, no MUFU)
#pragma unroll
        for (int k = 0; k < NPOW; k++) {
            if (t & (1 << k)) {
                float pr = sPr[k][n], pi = sPi[k][n];
                float r  = wr * pr - wi * pi;
                float im = wr * pi + wi * pr;
                wr = r; wi = im;
            }
        }

        // 16 geometric steps: acc[j] += Re(w); w *= dA
#pragma unroll
        for (int j = 0; j < LPT; j++) {
            acc[j] += wr;
            float r  = wr * ar - wi * ai;
            float im = wr * ai + wi * ar;
            wr = r; wi = im;
        }
    }

    // 16 consecutive floats per thread -> 4x STG.128, 64B-aligned
    float4* out = reinterpret_cast<float4*>(K + h * LL + t * LPT);
#pragma unroll
    for (int j = 0; j < LPT / 4; j++) {
        out[j] = make_float4(acc[4 * j], acc[4 * j + 1],
                             acc[4 * j + 2], acc[4 * j + 3]);
    }
}

// ---------------------------------------------------------------------------
extern "C" void kernel_launch(void* const* d_in, const int* in_sizes, int n_in,
                              void* d_out, int out_size) {
    const float* C_ri   = (const float*)d_in[0];
    const float* log_dt = (const float*)d_in[1];
    const float* B_ri   = (const float*)d_in[2];
    const float* invA   = (const float*)d_in[3];
    const float* Aim    = (const float*)d_in[4];

    int n_ssm = in_sizes[3] / NN;   // inv_A_real is (n_ssm, N)
    if (n_ssm <= 0) n_ssm = HH;

    ssd_setup_kernel<<<(HH * NN + 255) / 256, 256>>>(C_ri, log_dt, B_ri,
                                                     invA, Aim, n_ssm);
    ssd_main_kernel<<<HH, TPB>>>((float*)d_out);
}